// round 13
// baseline (speedup 1.0000x reference)
#include <cuda_runtime.h>
#include <cstdint>

// Problem constants
#define B_    2
#define S_    2048
#define H_    16
#define DM_   2048
#define DQK_  128
#define DV_   85
#define NV_   2720     // DV*H*2
#define HV_   1360     // DV*H
#define MROWS 4096     // B*S
#define SCALE_ 0.08838834764831845f  // 128^-0.5
#define NEGINF_ -1e30f

// ---------------- scratch (device globals; no allocation allowed) ----------
__device__ float  g_qp[MROWS * DM_];    // q @ Wq + bq        (B,S,2048)
__device__ float  g_kp[MROWS * DM_];    // k @ Wk + bk        (B,S,2048)
__device__ float  g_vp[MROWS * NV_];    // v @ Wv + bv        (B,S,2720)
__device__ float  g_vg[MROWS * HV_];    // gated V            (B,S,1360)
__device__ float  g_o [MROWS * HV_];    // attention out      (B,S,1360)
__device__ float2 g_rope[S_ * 64];      // (cos, sin) per (position, freq)

// ---------------- RoPE table: ZERO libm calls ------------------------------
// r = 10000^(-1/64) from 6 double sqrts (inline HW sequences, no tables).
// inv_freq[j] = r^j by repeated double multiply.
// ang formed in float32 (matches JAX rounding), reduced mod 2pi in double via
// floor (single cvt.rmi), mapped to [-pi, pi), then MUFU __sinf/__cosf.
__global__ __launch_bounds__(256) void rope_table_kernel()
{
    // 10000^(1/64) via sqrt chain: 10000^(1/2^6)
    double t = 10000.0;
    t = sqrt(t); t = sqrt(t); t = sqrt(t);
    t = sqrt(t); t = sqrt(t); t = sqrt(t);
    const double r = 1.0 / t;          // 10000^(-1/64)

    for (int i = blockIdx.x * 256 + threadIdx.x; i < S_ * 64; i += gridDim.x * 256) {
        int s = i >> 6, j = i & 63;

        double invd = 1.0;
        for (int p = 0; p < j; p++) invd *= r;       // r^j, pure DMUL

        float inv = (float)invd;                     // float32, like reference
        float ang = (float)s * inv;                  // float32 product, like reference

        double u    = (double)ang * 0.15915494309189535;   // ang / (2*pi)
        double frac = u - floor(u);                        // [0,1)
        double red  = frac * 6.283185307179586;            // [0, 2*pi)
        if (red >= 3.141592653589793) red -= 6.283185307179586;  // [-pi, pi)

        float rf = (float)red;
        g_rope[i] = make_float2(__cosf(rf), __sinf(rf));
    }
}

// ---------------- FUSED projection: Q | K | V in ONE launch ----------------
// Column space [0, 6816): seg 0 = Q -> g_qp, seg 1 = K -> g_kp, seg 2 = V -> g_vp.
// 128x128 tile, BK=16, 256 threads, 8x8 microtile.
__global__ __launch_bounds__(256) void fused_proj(const float* __restrict__ q,
                                                  const float* __restrict__ k,
                                                  const float* __restrict__ v,
                                                  const float* __restrict__ Wq,
                                                  const float* __restrict__ bq,
                                                  const float* __restrict__ Wk,
                                                  const float* __restrict__ bk,
                                                  const float* __restrict__ Wv,
                                                  const float* __restrict__ bv)
{
    __shared__ float As[16][128];   // transposed: As[kk][m]
    __shared__ float Bs[16][128];   // Bs[kk][n]

    const int bm  = blockIdx.y * 128;
    const int bnG = blockIdx.x * 128;          // global column
    const int tid = threadIdx.x;
    const int tx  = tid & 15;
    const int ty  = tid >> 4;

    int bn, Nseg;
    const float *A, *W, *bias;
    float* dst;
    if (bnG < 2048)      { bn = bnG;        Nseg = 2048; A = q; W = Wq; bias = bq; dst = g_qp; }
    else if (bnG < 4096) { bn = bnG - 2048; Nseg = 2048; A = k; W = Wk; bias = bk; dst = g_kp; }
    else                 { bn = bnG - 4096; Nseg = NV_;  A = v; W = Wv; bias = bv; dst = g_vp; }

    float acc[8][8];
#pragma unroll
    for (int i = 0; i < 8; i++)
#pragma unroll
        for (int j = 0; j < 8; j++) acc[i][j] = 0.f;

    for (int k0 = 0; k0 < DM_; k0 += 16) {
#pragma unroll
        for (int i = 0; i < 2; i++) {
            int f   = tid + 256 * i;
            int row = f >> 2;
            int c4  = (f & 3) * 4;
            float4 a = *(const float4*)&A[(size_t)(bm + row) * DM_ + k0 + c4];
            As[c4 + 0][row] = a.x;
            As[c4 + 1][row] = a.y;
            As[c4 + 2][row] = a.z;
            As[c4 + 3][row] = a.w;
        }
#pragma unroll
        for (int i = 0; i < 2; i++) {
            int f  = tid + 256 * i;
            int kr = f >> 5;
            int c4 = (f & 31) * 4;
            float4 w = make_float4(0.f, 0.f, 0.f, 0.f);
            if (bn + c4 < Nseg)
                w = *(const float4*)&W[(size_t)(k0 + kr) * Nseg + bn + c4];
            *(float4*)&Bs[kr][c4] = w;
        }
        __syncthreads();

#pragma unroll
        for (int kk = 0; kk < 16; kk++) {
            float4 a0 = *(const float4*)&As[kk][ty * 4];
            float4 a1 = *(const float4*)&As[kk][64 + ty * 4];
            float4 b0 = *(const float4*)&Bs[kk][tx * 4];
            float4 b1 = *(const float4*)&Bs[kk][64 + tx * 4];
            float a[8] = {a0.x, a0.y, a0.z, a0.w, a1.x, a1.y, a1.z, a1.w};
            float b[8] = {b0.x, b0.y, b0.z, b0.w, b1.x, b1.y, b1.z, b1.w};
#pragma unroll
            for (int i = 0; i < 8; i++)
#pragma unroll
                for (int j = 0; j < 8; j++)
                    acc[i][j] += a[i] * b[j];
        }
        __syncthreads();
    }

#pragma unroll
    for (int i = 0; i < 8; i++) {
        int row = bm + ((i < 4) ? (ty * 4 + i) : (64 + ty * 4 + i - 4));
#pragma unroll
        for (int jh = 0; jh < 2; jh++) {
            int col = bn + jh * 64 + tx * 4;
            if (col < Nseg) {
                float4 o;
                o.x = acc[i][jh * 4 + 0] + bias[col + 0];
                o.y = acc[i][jh * 4 + 1] + bias[col + 1];
                o.z = acc[i][jh * 4 + 2] + bias[col + 2];
                o.w = acc[i][jh * 4 + 3] + bias[col + 3];
                *(float4*)&dst[(size_t)row * Nseg + col] = o;
            }
        }
    }
}

// ---------------- SwiGLU gate, natural layout (B,S,1360) -------------------
__global__ __launch_bounds__(256) void glu_kernel()
{
    int idx = blockIdx.x * 256 + threadIdx.x;
    if (idx >= MROWS * HV_) return;
    int row = idx / HV_;
    int c   = idx - row * HV_;
    float a = g_vp[(size_t)row * NV_ + c];
    float g = g_vp[(size_t)row * NV_ + HV_ + c];
    float sig = 1.0f / (1.0f + __expf(-g));
    g_vg[idx] = a * (g * sig);
}

// ---------------- causal attention with on-the-fly RoPE --------------------
// Block: 256 threads = 8 warps = 8 consecutive query rows, same (b,h).
__global__ __launch_bounds__(256) void attn_warp_kernel()
{
    __shared__ float sK[32 * DQK_];
    __shared__ float sV[32 * DV_];

    const int h    = blockIdx.y;
    const int b    = blockIdx.z;
    const int tid  = threadIdx.x;
    const int warp = tid >> 5;
    const int lane = tid & 31;
    const int r    = blockIdx.x * 8 + warp;

    const float* Qp = g_qp + ((size_t)(b * S_ + r)) * DM_ + h * DQK_;
    float2 cs0 = g_rope[r * 64 + lane];
    float2 cs1 = g_rope[r * 64 + lane + 32];
    float x0 = Qp[lane], x1 = Qp[lane + 32], x2 = Qp[lane + 64], x3 = Qp[lane + 96];
    float q0 = (x0 * cs0.x - x2 * cs0.y) * SCALE_;
    float q1 = (x1 * cs1.x - x3 * cs1.y) * SCALE_;
    float q2 = (x2 * cs0.x + x0 * cs0.y) * SCALE_;
    float q3 = (x3 * cs1.x + x1 * cs1.y) * SCALE_;

    float m = NEGINF_, l = 0.f;
    float a0 = 0.f, a1 = 0.f, a2 = 0.f;

    const int r_max   = blockIdx.x * 8 + 7;
    const int n_tiles = r_max / 32 + 1;

    for (int kt = 0; kt < n_tiles; kt++) {
        __syncthreads();
        for (int f = tid; f < 32 * DQK_; f += 256) {
            int j  = f >> 7;
            int d  = f & 127;
            int sg = kt * 32 + j;
            int df = d & 63;
            float2 cs = g_rope[sg * 64 + df];
            const float* Kp = g_kp + ((size_t)(b * S_ + sg)) * DM_ + h * DQK_;
            float xa = Kp[df], xb = Kp[df + 64];
            sK[f] = (d < 64) ? (xa * cs.x - xb * cs.y)
                             : (xb * cs.x + xa * cs.y);
        }
        for (int f = tid; f < 32 * DV_; f += 256) {
            int j = f / DV_;
            int c = f - j * DV_;
            int sg = kt * 32 + j;
            sV[f] = g_vg[((size_t)(b * S_ + sg)) * HV_ + h * DV_ + c];
        }
        __syncthreads();

        int jmax = r - kt * 32 + 1;
        if (jmax > 32) jmax = 32;
        for (int j = 0; j < jmax; j++) {
            const float* krow = sK + j * DQK_;
            float s = q0 * krow[lane] + q1 * krow[lane + 32]
                    + q2 * krow[lane + 64] + q3 * krow[lane + 96];
#pragma unroll
            for (int o = 16; o >= 1; o >>= 1)
                s += __shfl_xor_sync(0xffffffffu, s, o);

            float mnew = fmaxf(m, s);
            float corr = __expf(m - mnew);
            float p    = __expf(s - mnew);
            m = mnew;
            l = l * corr + p;
            const float* vrow = sV + j * DV_;
            a0 = a0 * corr + p * vrow[lane];
            a1 = a1 * corr + p * vrow[lane + 32];
            a2 = a2 * corr + p * ((lane + 64 < DV_) ? vrow[lane + 64] : 0.f);
        }
    }

    float invl = 1.0f / l;
    float* Og = g_o + ((size_t)(b * S_ + r)) * HV_ + h * DV_;
    Og[lane]      = a0 * invl;
    Og[lane + 32] = a1 * invl;
    if (lane + 64 < DV_) Og[lane + 64] = a2 * invl;
}

// ---------------- output GEMM: out = g_o @ Wo + bo -------------------------
__global__ __launch_bounds__(256) void gemm_out(const float* __restrict__ W,
                                                const float* __restrict__ bias,
                                                float* __restrict__ C)
{
    __shared__ float As[16][128];
    __shared__ float Bs[16][128];

    const int bm  = blockIdx.y * 128;
    const int bn  = blockIdx.x * 128;
    const int tid = threadIdx.x;
    const int tx  = tid & 15;
    const int ty  = tid >> 4;
    const int K   = HV_;     // 1360
    const int N   = DM_;     // 2048

    float acc[8][8];
#pragma unroll
    for (int i = 0; i < 8; i++)
#pragma unroll
        for (int j = 0; j < 8; j++) acc[i][j] = 0.f;

    for (int k0 = 0; k0 < K; k0 += 16) {
#pragma unroll
        for (int i = 0; i < 2; i++) {
            int f   = tid + 256 * i;
            int row = f >> 2;
            int c4  = (f & 3) * 4;
            float4 a = *(const float4*)&g_o[(size_t)(bm + row) * K + k0 + c4];
            As[c4 + 0][row] = a.x;
            As[c4 + 1][row] = a.y;
            As[c4 + 2][row] = a.z;
            As[c4 + 3][row] = a.w;
        }
#pragma unroll
        for (int i = 0; i < 2; i++) {
            int f  = tid + 256 * i;
            int kr = f >> 5;
            int c4 = (f & 31) * 4;
            *(float4*)&Bs[kr][c4] = *(const float4*)&W[(size_t)(k0 + kr) * N + bn + c4];
        }
        __syncthreads();

#pragma unroll
        for (int kk = 0; kk < 16; kk++) {
            float4 a0 = *(const float4*)&As[kk][ty * 4];
            float4 a1 = *(const float4*)&As[kk][64 + ty * 4];
            float4 b0 = *(const float4*)&Bs[kk][tx * 4];
            float4 b1 = *(const float4*)&Bs[kk][64 + tx * 4];
            float a[8] = {a0.x, a0.y, a0.z, a0.w, a1.x, a1.y, a1.z, a1.w};
            float b[8] = {b0.x, b0.y, b0.z, b0.w, b1.x, b1.y, b1.z, b1.w};
#pragma unroll
            for (int i = 0; i < 8; i++)
#pragma unroll
                for (int j = 0; j < 8; j++)
                    acc[i][j] += a[i] * b[j];
        }
        __syncthreads();
    }

#pragma unroll
    for (int i = 0; i < 8; i++) {
        int row = bm + ((i < 4) ? (ty * 4 + i) : (64 + ty * 4 + i - 4));
#pragma unroll
        for (int jh = 0; jh < 2; jh++) {
            int col = bn + jh * 64 + tx * 4;
            float4 o;
            o.x = acc[i][jh * 4 + 0] + bias[col + 0];
            o.y = acc[i][jh * 4 + 1] + bias[col + 1];
            o.z = acc[i][jh * 4 + 2] + bias[col + 2];
            o.w = acc[i][jh * 4 + 3] + bias[col + 3];
            *(float4*)&C[(size_t)row * N + col] = o;
        }
    }
}

// ---------------- host launcher --------------------------------------------
extern "C" void kernel_launch(void* const* d_in, const int* in_sizes, int n_in,
                              void* d_out, int out_size)
{
    const float* q  = (const float*)d_in[0];
    const float* k  = (const float*)d_in[1];
    const float* v  = (const float*)d_in[2];
    // d_in[3] = mask (causal, implicit)
    const float* Wq = (const float*)d_in[4];
    const float* bq = (const float*)d_in[5];
    const float* Wk = (const float*)d_in[6];
    const float* bk = (const float*)d_in[7];
    const float* Wv = (const float*)d_in[8];
    const float* bv = (const float*)d_in[9];
    const float* Wo = (const float*)d_in[10];
    const float* bo = (const float*)d_in[11];
    float* out = (float*)d_out;

    dim3 blk(256);

    // RoPE table (no libm anywhere)
    rope_table_kernel<<<128, blk>>>();

    // Q, K, V projections in one launch
    fused_proj<<<dim3(54, MROWS / 128), blk>>>(q, k, v, Wq, bq, Wk, bk, Wv, bv);

    // SwiGLU gate
    glu_kernel<<<(MROWS * HV_ + 255) / 256, blk>>>();

    // Attention
    attn_warp_kernel<<<dim3(S_ / 8, H_, B_), blk>>>();

    // Output projection
    gemm_out<<<dim3(DM_ / 128, MROWS / 128), blk>>>(Wo, bo, out);
}

// round 17
// speedup vs baseline: 1.1483x; 1.1483x over previous
#include <cuda_runtime.h>
#include <cuda_bf16.h>
#include <cstdint>

// Problem constants
#define B_    2
#define S_    2048
#define H_    16
#define DM_   2048
#define DQK_  128
#define DV_   85
#define NV_   2720     // DV*H*2
#define HV_   1360     // DV*H
#define MROWS 4096     // B*S
#define SCALE_ 0.08838834764831845f  // 128^-0.5
#define NEGINF_ -1e30f

// ---------------- scratch (device globals; no allocation allowed) ----------
__device__ float  g_qp[MROWS * DM_];    // q @ Wq + bq        (B,S,2048)
__device__ float  g_kp[MROWS * DM_];    // k @ Wk + bk        (B,S,2048)
__device__ float  g_vp[MROWS * NV_];    // v @ Wv + bv        (B,S,2720)
__device__ float  g_vg[MROWS * HV_];    // gated V            (B,S,1360)
__device__ float  g_o [MROWS * HV_];    // attention out      (B,S,1360)
__device__ float2 g_rope[S_ * 64];      // (cos, sin) per (position, freq)

// ---------------- mma.sync m16n8k16 bf16 -> fp32 (sm_80+ portable) ---------
__device__ __forceinline__ void mma16816(float* d,
                                         uint32_t a0, uint32_t a1, uint32_t a2, uint32_t a3,
                                         uint32_t b0, uint32_t b1)
{
    asm volatile(
        "mma.sync.aligned.m16n8k16.row.col.f32.bf16.bf16.f32 "
        "{%0,%1,%2,%3}, {%4,%5,%6,%7}, {%8,%9}, {%0,%1,%2,%3};"
        : "+f"(d[0]), "+f"(d[1]), "+f"(d[2]), "+f"(d[3])
        : "r"(a0), "r"(a1), "r"(a2), "r"(a3), "r"(b0), "r"(b1));
}

// ============ tensor-core GEMM tile: C[bm:+128, bn:+128] = A@W + bias ======
// bf16x3 split (A0B0 + A0B1 + A1B0). 256 threads = 8 warps (2x4), warp tile
// 64x32, BK=32. Static smem 40KB: A-hi/lo [128][40], B^T-hi/lo [128][40].
__device__ __forceinline__ void mm_tile(const float* __restrict__ A,
                                        const float* __restrict__ W,
                                        const float* __restrict__ bias,
                                        float* __restrict__ C,
                                        int K, int Nseg, int bm, int bn)
{
    __shared__ __nv_bfloat16 sA0[128][40];
    __shared__ __nv_bfloat16 sA1[128][40];
    __shared__ __nv_bfloat16 sB0[128][40];   // [n][k]
    __shared__ __nv_bfloat16 sB1[128][40];

    const int tid  = threadIdx.x;
    const int wid  = tid >> 5;
    const int lane = tid & 31;
    const int wm   = wid & 1;      // 0..1  (64-row halves)
    const int wn   = wid >> 1;     // 0..3  (32-col quarters)
    const int lr   = lane >> 2;    // 0..7
    const int lc   = (lane & 3) * 2;

    float acc[4][4][4];
#pragma unroll
    for (int mt = 0; mt < 4; mt++)
#pragma unroll
        for (int nt = 0; nt < 4; nt++)
#pragma unroll
            for (int e = 0; e < 4; e++) acc[mt][nt][e] = 0.f;

    for (int k0 = 0; k0 < K; k0 += 32) {
        __syncthreads();   // previous compute done before restaging

        // Stage A tile [128 rows][32 k] (coalesced: 32 consecutive k per row)
        for (int i = tid; i < 4096; i += 256) {
            int row = i >> 5, c = i & 31;
            int kk = k0 + c;
            float x = (kk < K) ? A[(size_t)(bm + row) * K + kk] : 0.f;
            __nv_bfloat16 h = __float2bfloat16(x);
            __nv_bfloat16 l = __float2bfloat16(x - __bfloat162float(h));
            sA0[row][c] = h;
            sA1[row][c] = l;
        }
        // Stage B^T tile [128 n][32 k] (coalesced over n)
        for (int i = tid; i < 4096; i += 256) {
            int kc = i >> 7, n = i & 127;
            int kk = k0 + kc;
            float x = (kk < K && bn + n < Nseg) ? W[(size_t)kk * Nseg + bn + n] : 0.f;
            __nv_bfloat16 h = __float2bfloat16(x);
            __nv_bfloat16 l = __float2bfloat16(x - __bfloat162float(h));
            sB0[n][kc] = h;
            sB1[n][kc] = l;
        }
        __syncthreads();

#pragma unroll
        for (int ks = 0; ks < 2; ks++) {
            const int kb = ks * 16;
            // B fragments for 4 n-tiles (hi and lo)
            uint32_t b0h[4], b1h[4], b0l[4], b1l[4];
#pragma unroll
            for (int nt = 0; nt < 4; nt++) {
                int N = wn * 32 + nt * 8 + lr;
                b0h[nt] = *(const uint32_t*)&sB0[N][kb + lc];
                b1h[nt] = *(const uint32_t*)&sB0[N][kb + 8 + lc];
                b0l[nt] = *(const uint32_t*)&sB1[N][kb + lc];
                b1l[nt] = *(const uint32_t*)&sB1[N][kb + 8 + lc];
            }
#pragma unroll
            for (int mt = 0; mt < 4; mt++) {
                int R = wm * 64 + mt * 16 + lr;
                uint32_t a0h = *(const uint32_t*)&sA0[R][kb + lc];
                uint32_t a1h = *(const uint32_t*)&sA0[R + 8][kb + lc];
                uint32_t a2h = *(const uint32_t*)&sA0[R][kb + 8 + lc];
                uint32_t a3h = *(const uint32_t*)&sA0[R + 8][kb + 8 + lc];
                uint32_t a0l = *(const uint32_t*)&sA1[R][kb + lc];
                uint32_t a1l = *(const uint32_t*)&sA1[R + 8][kb + lc];
                uint32_t a2l = *(const uint32_t*)&sA1[R][kb + 8 + lc];
                uint32_t a3l = *(const uint32_t*)&sA1[R + 8][kb + 8 + lc];
#pragma unroll
                for (int nt = 0; nt < 4; nt++) {
                    mma16816(acc[mt][nt], a0h, a1h, a2h, a3h, b0h[nt], b1h[nt]);
                    mma16816(acc[mt][nt], a0h, a1h, a2h, a3h, b0l[nt], b1l[nt]);
                    mma16816(acc[mt][nt], a0l, a1l, a2l, a3l, b0h[nt], b1h[nt]);
                }
            }
        }
    }

    // Epilogue: d0,d1 -> (row lr, cols lc,lc+1); d2,d3 -> row lr+8.
#pragma unroll
    for (int mt = 0; mt < 4; mt++) {
#pragma unroll
        for (int nt = 0; nt < 4; nt++) {
            int R = bm + wm * 64 + mt * 16 + lr;
            int Ncol = bn + wn * 32 + nt * 8 + lc;
            if (Ncol < Nseg) {
                C[(size_t)R * Nseg + Ncol]           = acc[mt][nt][0] + bias[Ncol];
                C[(size_t)(R + 8) * Nseg + Ncol]     = acc[mt][nt][2] + bias[Ncol];
                if (Ncol + 1 < Nseg) {
                    C[(size_t)R * Nseg + Ncol + 1]       = acc[mt][nt][1] + bias[Ncol + 1];
                    C[(size_t)(R + 8) * Nseg + Ncol + 1] = acc[mt][nt][3] + bias[Ncol + 1];
                }
            }
        }
    }
}

// ---------------- fused Q|K|V projection (tensor cores) --------------------
__global__ __launch_bounds__(256) void proj_tc(const float* __restrict__ q,
                                               const float* __restrict__ k,
                                               const float* __restrict__ v,
                                               const float* __restrict__ Wq,
                                               const float* __restrict__ bq,
                                               const float* __restrict__ Wk,
                                               const float* __restrict__ bk,
                                               const float* __restrict__ Wv,
                                               const float* __restrict__ bv)
{
    const int t  = blockIdx.x;
    const int bm = blockIdx.y * 128;
    const float *A, *W, *bias;
    float* C;
    int Nseg, bn;
    if (t < 16)      { A = q; W = Wq; bias = bq; C = g_qp; Nseg = 2048; bn = t * 128; }
    else if (t < 32) { A = k; W = Wk; bias = bk; C = g_kp; Nseg = 2048; bn = (t - 16) * 128; }
    else             { A = v; W = Wv; bias = bv; C = g_vp; Nseg = NV_;  bn = (t - 32) * 128; }
    mm_tile(A, W, bias, C, DM_, Nseg, bm, bn);
}

// ---------------- output projection (tensor cores) -------------------------
__global__ __launch_bounds__(256) void out_tc(const float* __restrict__ Wo,
                                              const float* __restrict__ bo,
                                              float* __restrict__ out)
{
    mm_tile(g_o, Wo, bo, out, HV_, DM_, blockIdx.y * 128, blockIdx.x * 128);
}

// ---------------- RoPE table: ZERO libm calls (proven) ---------------------
__global__ __launch_bounds__(256) void rope_table_kernel()
{
    double t = 10000.0;
    t = sqrt(t); t = sqrt(t); t = sqrt(t);
    t = sqrt(t); t = sqrt(t); t = sqrt(t);
    const double r = 1.0 / t;          // 10000^(-1/64)

    for (int i = blockIdx.x * 256 + threadIdx.x; i < S_ * 64; i += gridDim.x * 256) {
        int s = i >> 6, j = i & 63;
        double invd = 1.0;
        for (int p = 0; p < j; p++) invd *= r;
        float inv = (float)invd;
        float ang = (float)s * inv;
        double u    = (double)ang * 0.15915494309189535;
        double frac = u - floor(u);
        double red  = frac * 6.283185307179586;
        if (red >= 3.141592653589793) red -= 6.283185307179586;
        float rf = (float)red;
        g_rope[i] = make_float2(__cosf(rf), __sinf(rf));
    }
}

// ---------------- SwiGLU gate, natural layout (B,S,1360) -------------------
__global__ __launch_bounds__(256) void glu_kernel()
{
    int idx = blockIdx.x * 256 + threadIdx.x;
    if (idx >= MROWS * HV_) return;
    int row = idx / HV_;
    int c   = idx - row * HV_;
    float a = g_vp[(size_t)row * NV_ + c];
    float g = g_vp[(size_t)row * NV_ + HV_ + c];
    float sig = 1.0f / (1.0f + __expf(-g));
    g_vg[idx] = a * (g * sig);
}

// ---------------- causal attention with on-the-fly RoPE (proven) -----------
__global__ __launch_bounds__(256) void attn_warp_kernel()
{
    __shared__ float sK[32 * DQK_];
    __shared__ float sV[32 * DV_];

    const int h    = blockIdx.y;
    const int b    = blockIdx.z;
    const int tid  = threadIdx.x;
    const int warp = tid >> 5;
    const int lane = tid & 31;
    const int r    = blockIdx.x * 8 + warp;

    const float* Qp = g_qp + ((size_t)(b * S_ + r)) * DM_ + h * DQK_;
    float2 cs0 = g_rope[r * 64 + lane];
    float2 cs1 = g_rope[r * 64 + lane + 32];
    float x0 = Qp[lane], x1 = Qp[lane + 32], x2 = Qp[lane + 64], x3 = Qp[lane + 96];
    float q0 = (x0 * cs0.x - x2 * cs0.y) * SCALE_;
    float q1 = (x1 * cs1.x - x3 * cs1.y) * SCALE_;
    float q2 = (x2 * cs0.x + x0 * cs0.y) * SCALE_;
    float q3 = (x3 * cs1.x + x1 * cs1.y) * SCALE_;

    float m = NEGINF_, l = 0.f;
    float a0 = 0.f, a1 = 0.f, a2 = 0.f;

    const int r_max   = blockIdx.x * 8 + 7;
    const int n_tiles = r_max / 32 + 1;

    for (int kt = 0; kt < n_tiles; kt++) {
        __syncthreads();
        for (int f = tid; f < 32 * DQK_; f += 256) {
            int j  = f >> 7;
            int d  = f & 127;
            int sg = kt * 32 + j;
            int df = d & 63;
            float2 cs = g_rope[sg * 64 + df];
            const float* Kp = g_kp + ((size_t)(b * S_ + sg)) * DM_ + h * DQK_;
            float xa = Kp[df], xb = Kp[df + 64];
            sK[f] = (d < 64) ? (xa * cs.x - xb * cs.y)
                             : (xb * cs.x + xa * cs.y);
        }
        for (int f = tid; f < 32 * DV_; f += 256) {
            int j = f / DV_;
            int c = f - j * DV_;
            int sg = kt * 32 + j;
            sV[f] = g_vg[((size_t)(b * S_ + sg)) * HV_ + h * DV_ + c];
        }
        __syncthreads();

        int jmax = r - kt * 32 + 1;
        if (jmax > 32) jmax = 32;
        for (int j = 0; j < jmax; j++) {
            const float* krow = sK + j * DQK_;
            float s = q0 * krow[lane] + q1 * krow[lane + 32]
                    + q2 * krow[lane + 64] + q3 * krow[lane + 96];
#pragma unroll
            for (int o = 16; o >= 1; o >>= 1)
                s += __shfl_xor_sync(0xffffffffu, s, o);

            float mnew = fmaxf(m, s);
            float corr = __expf(m - mnew);
            float p    = __expf(s - mnew);
            m = mnew;
            l = l * corr + p;
            const float* vrow = sV + j * DV_;
            a0 = a0 * corr + p * vrow[lane];
            a1 = a1 * corr + p * vrow[lane + 32];
            a2 = a2 * corr + p * ((lane + 64 < DV_) ? vrow[lane + 64] : 0.f);
        }
    }

    float invl = 1.0f / l;
    float* Og = g_o + ((size_t)(b * S_ + r)) * HV_ + h * DV_;
    Og[lane]      = a0 * invl;
    Og[lane + 32] = a1 * invl;
    if (lane + 64 < DV_) Og[lane + 64] = a2 * invl;
}

// ---------------- host launcher --------------------------------------------
extern "C" void kernel_launch(void* const* d_in, const int* in_sizes, int n_in,
                              void* d_out, int out_size)
{
    const float* q  = (const float*)d_in[0];
    const float* k  = (const float*)d_in[1];
    const float* v  = (const float*)d_in[2];
    // d_in[3] = mask (causal, implicit)
    const float* Wq = (const float*)d_in[4];
    const float* bq = (const float*)d_in[5];
    const float* Wk = (const float*)d_in[6];
    const float* bk = (const float*)d_in[7];
    const float* Wv = (const float*)d_in[8];
    const float* bv = (const float*)d_in[9];
    const float* Wo = (const float*)d_in[10];
    const float* bo = (const float*)d_in[11];
    float* out = (float*)d_out;

    dim3 blk(256);

    // RoPE table (no libm anywhere)
    rope_table_kernel<<<128, blk>>>();

    // Q, K, V projections: tensor cores (mma.sync), one launch
    proj_tc<<<dim3(54, MROWS / 128), blk>>>(q, k, v, Wq, bq, Wk, bk, Wv, bv);

    // SwiGLU gate
    glu_kernel<<<(MROWS * HV_ + 255) / 256, blk>>>();

    // Attention
    attn_warp_kernel<<<dim3(S_ / 8, H_, B_), blk>>>();

    // Output projection: tensor cores
    out_tc<<<dim3(DM_ / 128, MROWS / 128), blk>>>(Wo, bo, out);
}